// round 8
// baseline (speedup 1.0000x reference)
#include <cuda_runtime.h>
#include <cstdint>

// ---------------------------------------------------------------------------
// Attention2D fused — Round 8 (third submit of the occupancy-push kernel;
// R6/R7 both died to broker container failures with zero signal).
//   TPC=2 (32 rows/CTA), 512 thr, __launch_bounds__(512,2) -> 2 CTAs/SM,
//   32 warps. A staged raw fp32 k-permuted (fragment pair = one LDS.64);
//   tf32 hi/lo (3xTF32) split in registers. Results alias dead A-stage.
// ---------------------------------------------------------------------------

#define CDIM    256
#define HIDD    32
#define MTOK    16
#define TPC     2                    // tokens per CTA
#define RPC     (TPC * MTOK)         // 32 rows per CTA
#define SKS     260                  // result smem row stride
#define AST     264                  // A-stage row stride
#define HS      36
#define NTOK    16384
#define NTHR    512
#define NKSTEP  (CDIM / 8)

#define BIGF    (2 * RPC * SKS)
#define SMEM_FLOATS (BIGF + RPC*HS + TPC*CDIM + TPC*SKS + TPC*SKS + RPC*4 + RPC)
#define SMEM_BYTES  (SMEM_FLOATS * 4)

__device__ float g_Ws2[CDIM * CDIM];

__device__ __forceinline__ uint32_t f2tf32(float x) {
    uint32_t r;
    asm("cvt.rna.tf32.f32 %0, %1;" : "=r"(r) : "f"(x));
    return r;
}

__device__ __forceinline__ void mma8(float* d, const uint32_t* a,
                                     uint32_t b0, uint32_t b1) {
    asm volatile(
        "mma.sync.aligned.m16n8k8.row.col.f32.tf32.tf32.f32 "
        "{%0,%1,%2,%3}, {%4,%5,%6,%7}, {%8,%9}, {%0,%1,%2,%3};"
        : "+f"(d[0]), "+f"(d[1]), "+f"(d[2]), "+f"(d[3])
        : "r"(a[0]), "r"(a[1]), "r"(a[2]), "r"(a[3]), "r"(b0), "r"(b1));
}

// ---------------------------------------------------------------------------
__global__ void ws2_kernel(const float* __restrict__ Ws) {
    __shared__ float row[CDIM];
    const int r = blockIdx.x, c = threadIdx.x;
    row[c] = Ws[r * CDIM + c];
    __syncthreads();
    float acc = 0.f;
#pragma unroll 8
    for (int kk = 0; kk < CDIM; kk++)
        acc = fmaf(row[kk], __ldg(Ws + kk * CDIM + c), acc);
    g_Ws2[r * CDIM + c] = acc;
}

// ---------------------------------------------------------------------------
__global__ __launch_bounds__(NTHR, 2)
void fused_kernel(const float* __restrict__ q,   const float* __restrict__ k,
                  const float* __restrict__ pos, const int*   __restrict__ mask,
                  const float* __restrict__ Ws,
                  const float* __restrict__ Wp1, const float* __restrict__ bp1,
                  const float* __restrict__ Wp2, const float* __restrict__ bp2,
                  const float* __restrict__ Wa1, const float* __restrict__ ba1,
                  const float* __restrict__ Wa2, const float* __restrict__ ba2,
                  const float* __restrict__ Wo,  const float* __restrict__ bo,
                  float* __restrict__ out)
{
    extern __shared__ float sm[];
    float* sm_big  = sm;                         // A-stage -> s1/ai/logits
    float* sm_res2 = sm_big + RPC * SKS;         // s2 -> vv
    float* sm_h    = sm_big + BIGF;              // pos hidden -> attn hidden
    float* sm_qr   = sm_h   + RPC * HS;
    float* sm_qp   = sm_qr  + TPC * CDIM;
    float* sm_y    = sm_qp  + TPC * SKS;
    float* sm_pos  = sm_y   + TPC * SKS;
    int*   sm_mask = (int*)(sm_pos + RPC * 4);

    const int tid = threadIdx.x;
    const int tq  = blockIdx.x * TPC;
    const int r0g = tq * MTOK;

    // ---- stage: A raw fp32, k-permuted (k%8: 0..3 -> even slots, 4..7 -> odd)
    {
        const float* kp = k + (long)r0g * CDIM;
#pragma unroll
        for (int rep = 0; rep < 4; rep++) {
            const int idx = tid + rep * NTHR;          // RPC*64 = 2048
            const int m = idx >> 6, c4 = idx & 63;
            float4 v = __ldg((const float4*)(kp + m * CDIM) + c4);
            const int kk  = c4 * 4;
            const int off = m * AST + (kk & ~7) + ((kk & 4) ? 1 : 0);
            sm_big[off + 0] = v.x;
            sm_big[off + 2] = v.y;
            sm_big[off + 4] = v.z;
            sm_big[off + 6] = v.w;
        }
        if (tid < TPC * 64) {
            const int t = tid >> 6, c4 = tid & 63;
            float4 v = __ldg((const float4*)(q + (long)(tq + t) * CDIM) + c4);
            *(float4*)(sm_qr + t * CDIM + c4 * 4) = v;
        }
        if (tid < RPC) {
            float4 pv = __ldg((const float4*)pos + (r0g + tid));
            *(float4*)(sm_pos + tid * 4) = pv;
            sm_mask[tid] = __ldg(mask + r0g + tid);
        }
    }
    __syncthreads();

    // ---- dual GEMM (3xTF32): 8 warps -> s1 = k@Ws, 8 warps -> s2 = k@Ws2 --
    {
        const int wid  = tid >> 5, lane = tid & 31;
        const int gid  = lane >> 2, tig = lane & 3;
        const float* Bmat = (wid < 8) ? Ws : g_Ws2;
        const int ncb = (wid & 7) * 32;

        float d[2][4][4];
#pragma unroll
        for (int mi = 0; mi < 2; mi++)
#pragma unroll
            for (int ni = 0; ni < 4; ni++)
#pragma unroll
                for (int c = 0; c < 4; c++) d[mi][ni][c] = 0.f;

        for (int ks = 0; ks < NKSTEP; ks++) {
            const int k0 = ks * 8;
            uint32_t bh0[4], bh1[4], bl0[4], bl1[4];
#pragma unroll
            for (int ni = 0; ni < 4; ni++) {
                const int bc = ncb + ni * 8 + gid;
                const float b0f = __ldg(Bmat + (k0 + tig)     * CDIM + bc);
                const float b1f = __ldg(Bmat + (k0 + tig + 4) * CDIM + bc);
                bh0[ni] = f2tf32(b0f);
                bh1[ni] = f2tf32(b1f);
                bl0[ni] = f2tf32(b0f - __uint_as_float(bh0[ni]));
                bl1[ni] = f2tf32(b1f - __uint_as_float(bh1[ni]));
            }
#pragma unroll
            for (int mi = 0; mi < 2; mi++) {
                const float2 p0 = *(const float2*)(sm_big + (mi * 16 + gid) * AST + k0 + tig * 2);
                const float2 p1 = *(const float2*)(sm_big + (mi * 16 + gid + 8) * AST + k0 + tig * 2);
                uint32_t ah[4], al[4];
                ah[0] = f2tf32(p0.x); al[0] = f2tf32(p0.x - __uint_as_float(ah[0]));
                ah[1] = f2tf32(p1.x); al[1] = f2tf32(p1.x - __uint_as_float(ah[1]));
                ah[2] = f2tf32(p0.y); al[2] = f2tf32(p0.y - __uint_as_float(ah[2]));
                ah[3] = f2tf32(p1.y); al[3] = f2tf32(p1.y - __uint_as_float(ah[3]));
#pragma unroll
                for (int ni = 0; ni < 4; ni++) {
                    mma8(d[mi][ni], ah, bh0[ni], bh1[ni]);   // hi*hi
                    mma8(d[mi][ni], al, bh0[ni], bh1[ni]);   // lo*hi
                    mma8(d[mi][ni], ah, bl0[ni], bl1[ni]);   // hi*lo
                }
            }
        }
        __syncthreads();                 // A-stage dead; results may overwrite
        float* dst = (wid < 8) ? sm_big : sm_res2;
#pragma unroll
        for (int mi = 0; mi < 2; mi++)
#pragma unroll
            for (int ni = 0; ni < 4; ni++) {
                const int r0 = mi * 16 + gid;
                const int c0 = ncb + ni * 8 + 2 * tig;
                *(float2*)&dst[r0 * SKS + c0]       = make_float2(d[mi][ni][0], d[mi][ni][1]);
                *(float2*)&dst[(r0 + 8) * SKS + c0] = make_float2(d[mi][ni][2], d[mi][ni][3]);
            }
    }
    __syncthreads();

    const int cg = tid & 63;
    const int rg = tid >> 6;             // 0..7, 4 rows each

    // ---- E0: q_ = q @ Ws (512 outputs) ; E1: pos hidden -------------------
    {
        {
            const int t = tid >> 8, c = tid & 255;
            const float* qr = sm_qr + t * CDIM;
            float acc = 0.f;
#pragma unroll 8
            for (int cc = 0; cc < CDIM; cc++)
                acc = fmaf(qr[cc], __ldg(Ws + cc * CDIM + c), acc);
            sm_qp[t * SKS + c] = acc;
        }
        const int m  = tid >> 4;             // 0..31
        const int j2 = (tid & 15) * 2;
        const float p0 = sm_pos[m * 4 + 0], p1 = sm_pos[m * 4 + 1];
        const float p2 = sm_pos[m * 4 + 2], p3 = sm_pos[m * 4 + 3];
#pragma unroll
        for (int u = 0; u < 2; u++) {
            const int j = j2 + u;
            float h = __ldg(bp1 + j);
            h = fmaf(p0, __ldg(Wp1 +  0 + j), h);
            h = fmaf(p1, __ldg(Wp1 + 32 + j), h);
            h = fmaf(p2, __ldg(Wp1 + 64 + j), h);
            h = fmaf(p3, __ldg(Wp1 + 96 + j), h);
            sm_h[m * HS + j] = fmaxf(h, 0.f);
        }
    }
    __syncthreads();

    // ---- E2: posf ; ai = s1 - q_ + posf -> sm_big ; vv = s2 + posf --------
    {
        const int tokl = rg >> 2;        // rows rg*4..+3 -> token rg/4
        const float qp0 = sm_qp[tokl * SKS + cg * 4 + 0];
        const float qp1 = sm_qp[tokl * SKS + cg * 4 + 1];
        const float qp2 = sm_qp[tokl * SKS + cg * 4 + 2];
        const float qp3 = sm_qp[tokl * SKS + cg * 4 + 3];
        const float4 b2 = __ldg((const float4*)(bp2 + cg * 4));
#pragma unroll
        for (int i = 0; i < 4; i++) {
            const int m = rg * 4 + i;
            float4 pf = b2;
#pragma unroll 4
            for (int j = 0; j < HIDD; j++) {
                const float hv = sm_h[m * HS + j];
                const float4 w = __ldg((const float4*)(Wp2 + j * CDIM + cg * 4));
                pf.x = fmaf(hv, w.x, pf.x);
                pf.y = fmaf(hv, w.y, pf.y);
                pf.z = fmaf(hv, w.z, pf.z);
                pf.w = fmaf(hv, w.w, pf.w);
            }
            float4 s1v = *(const float4*)(sm_big  + m * SKS + cg * 4);
            float4 s2v = *(const float4*)(sm_res2 + m * SKS + cg * 4);
            float4 ai, vv;
            ai.x = s1v.x - qp0 + pf.x;  vv.x = s2v.x + pf.x;
            ai.y = s1v.y - qp1 + pf.y;  vv.y = s2v.y + pf.y;
            ai.z = s1v.z - qp2 + pf.z;  vv.z = s2v.z + pf.z;
            ai.w = s1v.w - qp3 + pf.w;  vv.w = s2v.w + pf.w;
            *(float4*)(sm_big  + m * SKS + cg * 4) = ai;
            *(float4*)(sm_res2 + m * SKS + cg * 4) = vv;
        }
    }
    __syncthreads();

    // ---- E3: h2 = relu(ai @ Wa1 + ba1) ------------------------------------
    {
        const int m  = tid >> 4;             // 0..31
        const int jp = (tid & 15) * 2;
        float2 acc = *(const float2*)(ba1 + jp);
        const float* as = sm_big + m * SKS;
#pragma unroll 4
        for (int c2 = 0; c2 < CDIM; c2++) {
            const float a = as[c2];
            const float2 w = __ldg((const float2*)(Wa1 + c2 * HIDD + jp));
            acc.x = fmaf(a, w.x, acc.x);
            acc.y = fmaf(a, w.y, acc.y);
        }
        acc.x = fmaxf(acc.x, 0.f);
        acc.y = fmaxf(acc.y, 0.f);
        *(float2*)(sm_h + m * HS + jp) = acc;   // sm_h reads all done (barrier above)
    }
    __syncthreads();

    // ---- E4: logits = h2 @ Wa2 + ba2, masked -> sm_big --------------------
    {
        const float4 b2 = __ldg((const float4*)(ba2 + cg * 4));
#pragma unroll
        for (int i = 0; i < 4; i++) {
            const int m = rg * 4 + i;
            float4 acc = b2;
#pragma unroll 4
            for (int j = 0; j < HIDD; j++) {
                const float hv = sm_h[m * HS + j];
                const float4 w = __ldg((const float4*)(Wa2 + j * CDIM + cg * 4));
                acc.x = fmaf(hv, w.x, acc.x);
                acc.y = fmaf(hv, w.y, acc.y);
                acc.z = fmaf(hv, w.z, acc.z);
                acc.w = fmaf(hv, w.w, acc.w);
            }
            if (sm_mask[m] == 0) { acc.x = -1e9f; acc.y = -1e9f; acc.z = -1e9f; acc.w = -1e9f; }
            *(float4*)(sm_big + m * SKS + cg * 4) = acc;
        }
    }
    __syncthreads();

    // ---- E5: per-channel softmax over M, weighted sum -> sm_y -------------
    {
        const int t = tid >> 8, c = tid & 255;
        const float* lp  = sm_big  + (t * MTOK) * SKS + c;
        const float* vpp = sm_res2 + (t * MTOK) * SKS + c;
        float mx = -3.4e38f;
#pragma unroll
        for (int m = 0; m < MTOK; m++) mx = fmaxf(mx, lp[m * SKS]);
        float s = 0.f, acc = 0.f;
#pragma unroll
        for (int m = 0; m < MTOK; m++) {
            const float e = __expf(lp[m * SKS] - mx);
            s += e;
            acc = fmaf(e, vpp[m * SKS], acc);
        }
        sm_y[t * SKS + c] = acc / s;
    }
    __syncthreads();

    // ---- E6: x = y @ Wo + bo ----------------------------------------------
    {
        const int t = tid >> 8, c = tid & 255;
        const float* yy = sm_y + t * SKS;
        float acc = __ldg(bo + c);
#pragma unroll 8
        for (int cc = 0; cc < CDIM; cc++)
            acc = fmaf(yy[cc], __ldg(Wo + cc * CDIM + c), acc);
        out[(long)(tq + t) * CDIM + c] = acc;
    }
}

// ---------------------------------------------------------------------------
extern "C" void kernel_launch(void* const* d_in, const int* in_sizes, int n_in,
                              void* d_out, int out_size) {
    const float* q   = (const float*)d_in[0];
    const float* k   = (const float*)d_in[1];
    const float* pos = (const float*)d_in[2];
    const int*   mask= (const int*)  d_in[3];
    const float* Ws  = (const float*)d_in[4];
    const float* Wp1 = (const float*)d_in[5];
    const float* bp1 = (const float*)d_in[6];
    const float* Wp2 = (const float*)d_in[7];
    const float* bp2 = (const float*)d_in[8];
    const float* Wa1 = (const float*)d_in[9];
    const float* ba1 = (const float*)d_in[10];
    const float* Wa2 = (const float*)d_in[11];
    const float* ba2 = (const float*)d_in[12];
    const float* Wo  = (const float*)d_in[13];
    const float* bo  = (const float*)d_in[14];
    float* out = (float*)d_out;

    cudaFuncSetAttribute(fused_kernel,
                         cudaFuncAttributeMaxDynamicSharedMemorySize, SMEM_BYTES);

    ws2_kernel<<<CDIM, CDIM>>>(Ws);
    fused_kernel<<<NTOK / TPC, NTHR, SMEM_BYTES>>>(
        q, k, pos, mask, Ws, Wp1, bp1, Wp2, bp2,
        Wa1, ba1, Wa2, ba2, Wo, bo, out);
}

// round 10
// speedup vs baseline: 1.1664x; 1.1664x over previous
#include <cuda_runtime.h>
#include <cstdint>

// ---------------------------------------------------------------------------
// Attention2D fused — Round 10 (R9 resubmit; broker died twice with zero
// signal). R8 skeleton (TPC=2, 2 CTAs/SM, 32 warps) + E2/E4 loop
// interchange: Wp2/Wa2 loaded once per j and reused across the thread's
// 4 rows -> 4x less epilogue weight LDG traffic vs measured L1=92.1%.
// ---------------------------------------------------------------------------

#define CDIM    256
#define HIDD    32
#define MTOK    16
#define TPC     2                    // tokens per CTA
#define RPC     (TPC * MTOK)         // 32 rows per CTA
#define SKS     260                  // result smem row stride
#define AST     264                  // A-stage row stride
#define HS      36
#define NTOK    16384
#define NTHR    512
#define NKSTEP  (CDIM / 8)

#define BIGF    (2 * RPC * SKS)
#define SMEM_FLOATS (BIGF + RPC*HS + TPC*CDIM + TPC*SKS + TPC*SKS + RPC*4 + RPC)
#define SMEM_BYTES  (SMEM_FLOATS * 4)

__device__ float g_Ws2[CDIM * CDIM];

__device__ __forceinline__ uint32_t f2tf32(float x) {
    uint32_t r;
    asm("cvt.rna.tf32.f32 %0, %1;" : "=r"(r) : "f"(x));
    return r;
}

__device__ __forceinline__ void mma8(float* d, const uint32_t* a,
                                     uint32_t b0, uint32_t b1) {
    asm volatile(
        "mma.sync.aligned.m16n8k8.row.col.f32.tf32.tf32.f32 "
        "{%0,%1,%2,%3}, {%4,%5,%6,%7}, {%8,%9}, {%0,%1,%2,%3};"
        : "+f"(d[0]), "+f"(d[1]), "+f"(d[2]), "+f"(d[3])
        : "r"(a[0]), "r"(a[1]), "r"(a[2]), "r"(a[3]), "r"(b0), "r"(b1));
}

// ---------------------------------------------------------------------------
__global__ void ws2_kernel(const float* __restrict__ Ws) {
    __shared__ float row[CDIM];
    const int r = blockIdx.x, c = threadIdx.x;
    row[c] = Ws[r * CDIM + c];
    __syncthreads();
    float acc = 0.f;
#pragma unroll 8
    for (int kk = 0; kk < CDIM; kk++)
        acc = fmaf(row[kk], __ldg(Ws + kk * CDIM + c), acc);
    g_Ws2[r * CDIM + c] = acc;
}

// ---------------------------------------------------------------------------
__global__ __launch_bounds__(NTHR, 2)
void fused_kernel(const float* __restrict__ q,   const float* __restrict__ k,
                  const float* __restrict__ pos, const int*   __restrict__ mask,
                  const float* __restrict__ Ws,
                  const float* __restrict__ Wp1, const float* __restrict__ bp1,
                  const float* __restrict__ Wp2, const float* __restrict__ bp2,
                  const float* __restrict__ Wa1, const float* __restrict__ ba1,
                  const float* __restrict__ Wa2, const float* __restrict__ ba2,
                  const float* __restrict__ Wo,  const float* __restrict__ bo,
                  float* __restrict__ out)
{
    extern __shared__ float sm[];
    float* sm_big  = sm;                         // A-stage -> s1/ai/logits
    float* sm_res2 = sm_big + RPC * SKS;         // s2 -> vv
    float* sm_h    = sm_big + BIGF;              // pos hidden -> attn hidden
    float* sm_qr   = sm_h   + RPC * HS;
    float* sm_qp   = sm_qr  + TPC * CDIM;
    float* sm_y    = sm_qp  + TPC * SKS;
    float* sm_pos  = sm_y   + TPC * SKS;
    int*   sm_mask = (int*)(sm_pos + RPC * 4);

    const int tid = threadIdx.x;
    const int tq  = blockIdx.x * TPC;
    const int r0g = tq * MTOK;

    // ---- stage: A raw fp32, k-permuted (k%8: 0..3 -> even slots, 4..7 -> odd)
    {
        const float* kp = k + (long)r0g * CDIM;
#pragma unroll
        for (int rep = 0; rep < 4; rep++) {
            const int idx = tid + rep * NTHR;          // RPC*64 = 2048
            const int m = idx >> 6, c4 = idx & 63;
            float4 v = __ldg((const float4*)(kp + m * CDIM) + c4);
            const int kk  = c4 * 4;
            const int off = m * AST + (kk & ~7) + ((kk & 4) ? 1 : 0);
            sm_big[off + 0] = v.x;
            sm_big[off + 2] = v.y;
            sm_big[off + 4] = v.z;
            sm_big[off + 6] = v.w;
        }
        if (tid < TPC * 64) {
            const int t = tid >> 6, c4 = tid & 63;
            float4 v = __ldg((const float4*)(q + (long)(tq + t) * CDIM) + c4);
            *(float4*)(sm_qr + t * CDIM + c4 * 4) = v;
        }
        if (tid < RPC) {
            float4 pv = __ldg((const float4*)pos + (r0g + tid));
            *(float4*)(sm_pos + tid * 4) = pv;
            sm_mask[tid] = __ldg(mask + r0g + tid);
        }
    }
    __syncthreads();

    // ---- dual GEMM (3xTF32): 8 warps -> s1 = k@Ws, 8 warps -> s2 = k@Ws2 --
    {
        const int wid  = tid >> 5, lane = tid & 31;
        const int gid  = lane >> 2, tig = lane & 3;
        const float* Bmat = (wid < 8) ? Ws : g_Ws2;
        const int ncb = (wid & 7) * 32;

        float d[2][4][4];
#pragma unroll
        for (int mi = 0; mi < 2; mi++)
#pragma unroll
            for (int ni = 0; ni < 4; ni++)
#pragma unroll
                for (int c = 0; c < 4; c++) d[mi][ni][c] = 0.f;

        for (int ks = 0; ks < NKSTEP; ks++) {
            const int k0 = ks * 8;
            uint32_t bh0[4], bh1[4], bl0[4], bl1[4];
#pragma unroll
            for (int ni = 0; ni < 4; ni++) {
                const int bc = ncb + ni * 8 + gid;
                const float b0f = __ldg(Bmat + (k0 + tig)     * CDIM + bc);
                const float b1f = __ldg(Bmat + (k0 + tig + 4) * CDIM + bc);
                bh0[ni] = f2tf32(b0f);
                bh1[ni] = f2tf32(b1f);
                bl0[ni] = f2tf32(b0f - __uint_as_float(bh0[ni]));
                bl1[ni] = f2tf32(b1f - __uint_as_float(bh1[ni]));
            }
#pragma unroll
            for (int mi = 0; mi < 2; mi++) {
                const float2 p0 = *(const float2*)(sm_big + (mi * 16 + gid) * AST + k0 + tig * 2);
                const float2 p1 = *(const float2*)(sm_big + (mi * 16 + gid + 8) * AST + k0 + tig * 2);
                uint32_t ah[4], al[4];
                ah[0] = f2tf32(p0.x); al[0] = f2tf32(p0.x - __uint_as_float(ah[0]));
                ah[1] = f2tf32(p1.x); al[1] = f2tf32(p1.x - __uint_as_float(ah[1]));
                ah[2] = f2tf32(p0.y); al[2] = f2tf32(p0.y - __uint_as_float(ah[2]));
                ah[3] = f2tf32(p1.y); al[3] = f2tf32(p1.y - __uint_as_float(ah[3]));
#pragma unroll
                for (int ni = 0; ni < 4; ni++) {
                    mma8(d[mi][ni], ah, bh0[ni], bh1[ni]);   // hi*hi
                    mma8(d[mi][ni], al, bh0[ni], bh1[ni]);   // lo*hi
                    mma8(d[mi][ni], ah, bl0[ni], bl1[ni]);   // hi*lo
                }
            }
        }
        __syncthreads();                 // A-stage dead; results may overwrite
        float* dst = (wid < 8) ? sm_big : sm_res2;
#pragma unroll
        for (int mi = 0; mi < 2; mi++)
#pragma unroll
            for (int ni = 0; ni < 4; ni++) {
                const int r0 = mi * 16 + gid;
                const int c0 = ncb + ni * 8 + 2 * tig;
                *(float2*)&dst[r0 * SKS + c0]       = make_float2(d[mi][ni][0], d[mi][ni][1]);
                *(float2*)&dst[(r0 + 8) * SKS + c0] = make_float2(d[mi][ni][2], d[mi][ni][3]);
            }
    }
    __syncthreads();

    const int cg = tid & 63;
    const int rg = tid >> 6;             // 0..7, 4 rows each

    // ---- E0: q_ = q @ Ws (512 outputs) ; E1: pos hidden -------------------
    {
        {
            const int t = tid >> 8, c = tid & 255;
            const float* qr = sm_qr + t * CDIM;
            float acc = 0.f;
#pragma unroll 8
            for (int cc = 0; cc < CDIM; cc++)
                acc = fmaf(qr[cc], __ldg(Ws + cc * CDIM + c), acc);
            sm_qp[t * SKS + c] = acc;
        }
        const int m  = tid >> 4;             // 0..31
        const int j2 = (tid & 15) * 2;
        const float p0 = sm_pos[m * 4 + 0], p1 = sm_pos[m * 4 + 1];
        const float p2 = sm_pos[m * 4 + 2], p3 = sm_pos[m * 4 + 3];
#pragma unroll
        for (int u = 0; u < 2; u++) {
            const int j = j2 + u;
            float h = __ldg(bp1 + j);
            h = fmaf(p0, __ldg(Wp1 +  0 + j), h);
            h = fmaf(p1, __ldg(Wp1 + 32 + j), h);
            h = fmaf(p2, __ldg(Wp1 + 64 + j), h);
            h = fmaf(p3, __ldg(Wp1 + 96 + j), h);
            sm_h[m * HS + j] = fmaxf(h, 0.f);
        }
    }
    __syncthreads();

    // ---- E2 (interchanged): posf for 4 rows with Wp2 loaded once per j ----
    {
        const int tokl = rg >> 2;        // rows rg*4..+3 -> token rg/4
        const float qp0 = sm_qp[tokl * SKS + cg * 4 + 0];
        const float qp1 = sm_qp[tokl * SKS + cg * 4 + 1];
        const float qp2 = sm_qp[tokl * SKS + cg * 4 + 2];
        const float qp3 = sm_qp[tokl * SKS + cg * 4 + 3];
        const float4 b2 = __ldg((const float4*)(bp2 + cg * 4));
        float4 pf[4];
#pragma unroll
        for (int i = 0; i < 4; i++) pf[i] = b2;
        const float* hbase = sm_h + (rg * 4) * HS;
#pragma unroll 4
        for (int j = 0; j < HIDD; j++) {
            const float4 w = __ldg((const float4*)(Wp2 + j * CDIM + cg * 4));
#pragma unroll
            for (int i = 0; i < 4; i++) {
                const float hv = hbase[i * HS + j];
                pf[i].x = fmaf(hv, w.x, pf[i].x);
                pf[i].y = fmaf(hv, w.y, pf[i].y);
                pf[i].z = fmaf(hv, w.z, pf[i].z);
                pf[i].w = fmaf(hv, w.w, pf[i].w);
            }
        }
#pragma unroll
        for (int i = 0; i < 4; i++) {
            const int m = rg * 4 + i;
            float4 s1v = *(const float4*)(sm_big  + m * SKS + cg * 4);
            float4 s2v = *(const float4*)(sm_res2 + m * SKS + cg * 4);
            float4 ai, vv;
            ai.x = s1v.x - qp0 + pf[i].x;  vv.x = s2v.x + pf[i].x;
            ai.y = s1v.y - qp1 + pf[i].y;  vv.y = s2v.y + pf[i].y;
            ai.z = s1v.z - qp2 + pf[i].z;  vv.z = s2v.z + pf[i].z;
            ai.w = s1v.w - qp3 + pf[i].w;  vv.w = s2v.w + pf[i].w;
            *(float4*)(sm_big  + m * SKS + cg * 4) = ai;
            *(float4*)(sm_res2 + m * SKS + cg * 4) = vv;
        }
    }
    __syncthreads();

    // ---- E3: h2 = relu(ai @ Wa1 + ba1) ------------------------------------
    {
        const int m  = tid >> 4;             // 0..31
        const int jp = (tid & 15) * 2;
        float2 acc = *(const float2*)(ba1 + jp);
        const float* as = sm_big + m * SKS;
#pragma unroll 4
        for (int c2 = 0; c2 < CDIM; c2++) {
            const float a = as[c2];
            const float2 w = __ldg((const float2*)(Wa1 + c2 * HIDD + jp));
            acc.x = fmaf(a, w.x, acc.x);
            acc.y = fmaf(a, w.y, acc.y);
        }
        acc.x = fmaxf(acc.x, 0.f);
        acc.y = fmaxf(acc.y, 0.f);
        *(float2*)(sm_h + m * HS + jp) = acc;   // sm_h reads all done (barrier above)
    }
    __syncthreads();

    // ---- E4 (interchanged): logits for 4 rows with Wa2 loaded once per j --
    {
        const float4 b2 = __ldg((const float4*)(ba2 + cg * 4));
        float4 acc[4];
#pragma unroll
        for (int i = 0; i < 4; i++) acc[i] = b2;
        const float* hbase = sm_h + (rg * 4) * HS;
#pragma unroll 4
        for (int j = 0; j < HIDD; j++) {
            const float4 w = __ldg((const float4*)(Wa2 + j * CDIM + cg * 4));
#pragma unroll
            for (int i = 0; i < 4; i++) {
                const float hv = hbase[i * HS + j];
                acc[i].x = fmaf(hv, w.x, acc[i].x);
                acc[i].y = fmaf(hv, w.y, acc[i].y);
                acc[i].z = fmaf(hv, w.z, acc[i].z);
                acc[i].w = fmaf(hv, w.w, acc[i].w);
            }
        }
#pragma unroll
        for (int i = 0; i < 4; i++) {
            const int m = rg * 4 + i;
            float4 v = acc[i];
            if (sm_mask[m] == 0) { v.x = -1e9f; v.y = -1e9f; v.z = -1e9f; v.w = -1e9f; }
            *(float4*)(sm_big + m * SKS + cg * 4) = v;
        }
    }
    __syncthreads();

    // ---- E5: per-channel softmax over M, weighted sum -> sm_y -------------
    {
        const int t = tid >> 8, c = tid & 255;
        const float* lp  = sm_big  + (t * MTOK) * SKS + c;
        const float* vpp = sm_res2 + (t * MTOK) * SKS + c;
        float mx = -3.4e38f;
#pragma unroll
        for (int m = 0; m < MTOK; m++) mx = fmaxf(mx, lp[m * SKS]);
        float s = 0.f, acc = 0.f;
#pragma unroll
        for (int m = 0; m < MTOK; m++) {
            const float e = __expf(lp[m * SKS] - mx);
            s += e;
            acc = fmaf(e, vpp[m * SKS], acc);
        }
        sm_y[t * SKS + c] = acc / s;
    }
    __syncthreads();

    // ---- E6: x = y @ Wo + bo ----------------------------------------------
    {
        const int t = tid >> 8, c = tid & 255;
        const float* yy = sm_y + t * SKS;
        float acc = __ldg(bo + c);
#pragma unroll 8
        for (int cc = 0; cc < CDIM; cc++)
            acc = fmaf(yy[cc], __ldg(Wo + cc * CDIM + c), acc);
        out[(long)(tq + t) * CDIM + c] = acc;
    }
}

// ---------------------------------------------------------------------------
extern "C" void kernel_launch(void* const* d_in, const int* in_sizes, int n_in,
                              void* d_out, int out_size) {
    const float* q   = (const float*)d_in[0];
    const float* k   = (const float*)d_in[1];
    const float* pos = (const float*)d_in[2];
    const int*   mask= (const int*)  d_in[3];
    const float* Ws  = (const float*)d_in[4];
    const float* Wp1 = (const float*)d_in[5];
    const float* bp1 = (const float*)d_in[6];
    const float* Wp2 = (const float*)d_in[7];
    const float* bp2 = (const float*)d_in[8];
    const float* Wa1 = (const float*)d_in[9];
    const float* ba1 = (const float*)d_in[10];
    const float* Wa2 = (const float*)d_in[11];
    const float* ba2 = (const float*)d_in[12];
    const float* Wo  = (const float*)d_in[13];
    const float* bo  = (const float*)d_in[14];
    float* out = (float*)d_out;

    cudaFuncSetAttribute(fused_kernel,
                         cudaFuncAttributeMaxDynamicSharedMemorySize, SMEM_BYTES);

    ws2_kernel<<<CDIM, CDIM>>>(Ws);
    fused_kernel<<<NTOK / TPC, NTHR, SMEM_BYTES>>>(
        q, k, pos, mask, Ws, Wp1, bp1, Wp2, bp2,
        Wa1, ba1, Wa2, ba2, Wo, bo, out);
}